// round 15
// baseline (speedup 1.0000x reference)
#include <cuda_runtime.h>
#include <cuda_fp16.h>
#include <cstdint>

#define B_      256
#define N_      1024
#define DIN     64
#define HID     256
#define DOUT    128
#define MT      128
#define MAXTILE 2048             // worst case: all rows valid
#define SLOTS   10               // max tiles overlapping one batch (<=9) + pad
#define THREADS 256
#define NCHUNKS 9                // k64 chunks: 1 (K=64) + 4 + 4

// smem layout (bytes)
#define SM_B     0                       // 3 buffers x 32768 (B: [256 n][128B = k64 fp16])
#define SM_BIAS  98304                   // 2 * 256 * 4 (pb1, pb2)
#define SM_A     109568                  // A fp16: [128 m][512B row]
#define SM_ROWB  173056                  // 128 ints (row batch ids, epilogue-3)
#define SM_BYTES (109568 + 65536)        // 175104
// epilogue-3 pool buffer reuses bytes [0, 135168): 128 rows x 264 floats

__device__ float g_partial[B_ * SLOTS * HID];
__device__ __align__(16) __half g_wt[147456];
__device__ int g_cnt[B_];
__device__ int g_idx[B_ * N_];
__device__ int g_src[B_ * N_];           // global compacted rows: (b<<10)|n
__device__ int g_base[B_];               // b*SLOTS - (off_b>>7)
__device__ int g_total;
#define WT1 0
#define WT2 16384
#define WT3 81920

// ---------------------------------------------------------------------------
// helpers
// ---------------------------------------------------------------------------
__device__ __forceinline__ uint32_t smem_u32(const void* p) {
    uint32_t a;
    asm("{ .reg .u64 t; cvta.to.shared.u64 t, %1; cvt.u32.u64 %0, t; }"
        : "=r"(a) : "l"(p));
    return a;
}
__device__ __forceinline__ void ldm4(uint32_t r[4], uint32_t addr) {
    asm volatile("ldmatrix.sync.aligned.m8n8.x4.shared.b16 {%0,%1,%2,%3}, [%4];"
                 : "=r"(r[0]), "=r"(r[1]), "=r"(r[2]), "=r"(r[3]) : "r"(addr));
}
__device__ __forceinline__ void mma16816(float c[4], const uint32_t a[4],
                                         uint32_t b0, uint32_t b1) {
    asm volatile(
        "mma.sync.aligned.m16n8k16.row.col.f32.f16.f16.f32 "
        "{%0,%1,%2,%3}, {%4,%5,%6,%7}, {%8,%9}, {%0,%1,%2,%3};"
        : "+f"(c[0]), "+f"(c[1]), "+f"(c[2]), "+f"(c[3])
        : "r"(a[0]), "r"(a[1]), "r"(a[2]), "r"(a[3]), "r"(b0), "r"(b1));
}
__device__ __forceinline__ void cpasync16(uint32_t dst, const void* src) {
    asm volatile("cp.async.ca.shared.global [%0], [%1], 16;" :: "r"(dst), "l"(src));
}
#define CP_COMMIT() asm volatile("cp.async.commit_group;" ::: "memory")
#define CP_WAIT(N)  asm volatile("cp.async.wait_group %0;" :: "n"(N) : "memory")

// pack two fp32 -> f16x2 (v0 -> first element in memory)
__device__ __forceinline__ uint32_t cvt_h2(float v0, float v1) {
    uint32_t r;
    asm("cvt.rn.f16x2.f32 %0, %1, %2;" : "=r"(r) : "f"(v1), "f"(v0));
    return r;
}

// ---------------------------------------------------------------------------
// prep_all: blocks 0..575 weights; 576..831 per-batch compaction;
//           832..1087 zero g_partial
// ---------------------------------------------------------------------------
extern "C" __global__ void __launch_bounds__(256)
prep_all(const float* __restrict__ pw1, const float* __restrict__ pw2,
         const float* __restrict__ pw3, const int* __restrict__ mask)
{
    if (blockIdx.x < 576) {
        int i = blockIdx.x * 256 + threadIdx.x;
        if (i >= 147456) return;
        float v; int dst;
        if (i < 16384) {            // pw1 [64][256] -> [256][64]
            int k = i >> 8, n = i & 255;
            v = pw1[i]; dst = WT1 + n * 64 + k;
        } else if (i < 81920) {     // pw2 [256][256]
            int j = i - 16384; int k = j >> 8, n = j & 255;
            v = pw2[j]; dst = WT2 + n * 256 + k;
        } else {                    // pw3 [256][256]
            int j = i - 81920; int k = j >> 8, n = j & 255;
            v = pw3[j]; dst = WT3 + n * 256 + k;
        }
        g_wt[dst] = __float2half_rn(v);
    } else if (blockIdx.x < 832) {
        const int b = blockIdx.x - 576, tid = threadIdx.x;
        const int lane = tid & 31, wid = tid >> 5;
        const int* mb = mask + b * N_;
        int v[4]; int c = 0;
#pragma unroll
        for (int i = 0; i < 4; i++) { v[i] = (mb[tid * 4 + i] != 0); c += v[i]; }
        int pre = c;
#pragma unroll
        for (int d = 1; d < 32; d <<= 1) {
            int t = __shfl_up_sync(0xffffffffu, pre, d);
            if (lane >= d) pre += t;
        }
        __shared__ int wsum[8];
        if (lane == 31) wsum[wid] = pre;
        __syncthreads();
        int wbase = 0;
#pragma unroll
        for (int w = 0; w < 8; w++)
            if (w < wid) wbase += wsum[w];
        int o = wbase + pre - c;
#pragma unroll
        for (int i = 0; i < 4; i++)
            if (v[i]) g_idx[b * N_ + (o++)] = tid * 4 + i;
        if (tid == 255) g_cnt[b] = wbase + pre;
    } else {
        // zero g_partial slots for batch (blockIdx.x - 832)
        const int b = blockIdx.x - 832;
        float4* dst = (float4*)(g_partial + (size_t)b * SLOTS * HID);
        for (int i = threadIdx.x; i < 640; i += 256)
            dst[i] = make_float4(0.f, 0.f, 0.f, 0.f);
    }
}

// ---------------------------------------------------------------------------
// prep3: every block redundantly scans g_cnt; block b scatters its rows
// ---------------------------------------------------------------------------
extern "C" __global__ void __launch_bounds__(256)
prep3_scatter()
{
    const int b = blockIdx.x, tid = threadIdx.x;
    const int lane = tid & 31, wid = tid >> 5;
    __shared__ int s_excl[256];
    __shared__ int wsum[8];

    int c = g_cnt[tid];
    int pre = c;
#pragma unroll
    for (int d = 1; d < 32; d <<= 1) {
        int t = __shfl_up_sync(0xffffffffu, pre, d);
        if (lane >= d) pre += t;
    }
    if (lane == 31) wsum[wid] = pre;
    __syncthreads();
    int wbase = 0, total = 0;
#pragma unroll
    for (int w = 0; w < 8; w++) {
        if (w < wid) wbase += wsum[w];
        total += wsum[w];
    }
    s_excl[tid] = wbase + pre - c;       // exclusive prefix of batch tid
    __syncthreads();

    const int off = s_excl[b];
    const int cnt = g_cnt[b];
    if (tid == 0) {
        g_base[b] = b * SLOTS - (off >> 7);
        if (b == 0) g_total = total;
    }
    for (int i = tid; i < cnt; i += 256)
        g_src[off + i] = (b << 10) | g_idx[b * N_ + i];
}

// ---------------------------------------------------------------------------
// issue one B chunk (k64) via cp.async into ring buffer gi%3
// ---------------------------------------------------------------------------
__device__ __forceinline__ void issue_chunk(int gi, uint32_t sb, int tid)
{
    const __half* w; int K, kc;
    if (gi == 0)     { w = g_wt + WT1; K = 64;  kc = 0; }
    else if (gi < 5) { w = g_wt + WT2; K = 256; kc = gi - 1; }
    else             { w = g_wt + WT3; K = 256; kc = gi - 5; }
    int n = tid;
    uint32_t dst = sb + SM_B + (uint32_t)(gi % 3) * 32768u + (uint32_t)n * 128u;
    const char* src = (const char*)(w + (size_t)n * K + kc * 64);
#pragma unroll
    for (int c = 0; c < 8; c++)
        cpasync16(dst + ((uint32_t)(c ^ (n & 7)) << 4), src + c * 16);
}

// epilogue store into A smem (fp16), swizzled. chunk = 8-col (16B) group idx
__device__ __forceinline__ void store_one(char* smem, int row, int chunk, int t,
                                          float v0, float v1)
{
    uint32_t h2 = cvt_h2(v0, v1);
    uint32_t off = (uint32_t)row * 512u + ((uint32_t)(chunk ^ (row & 7)) << 4) + t * 4;
    *(uint32_t*)(smem + SM_A + off) = h2;
}

// ---------------------------------------------------------------------------
// phi kernel: globally compacted rows; fp16 MMA, 2(M)x4(N) warp grid;
// segmented pool epilogue
// ---------------------------------------------------------------------------
extern "C" __global__ void __launch_bounds__(THREADS, 1)
phi_kernel(const float* __restrict__ x,
           const float* __restrict__ pb1, const float* __restrict__ pb2,
           const float* __restrict__ pb3)
{
    const int tile = blockIdx.x;
    const int T = g_total;
    if (tile * MT >= T) return;

    extern __shared__ char smem[];
    uint32_t sb = smem_u32(smem);
    const int tid = threadIdx.x, wid = tid >> 5, lane = tid & 31;
    const int mw = wid >> 2, nw = wid & 3;       // 2 x 4 warp grid
    const int gg = lane >> 2, t = lane & 3;

    // issue chunk 0 as early as possible
    issue_chunk(0, sb, tid);
    CP_COMMIT();

    ((float*)(smem + SM_BIAS))[tid]       = pb1[tid];
    ((float*)(smem + SM_BIAS))[256 + tid] = pb2[tid];

    // ---- gather compacted rows -> A smem fp16; zero padding slots
    {
        int row = tid >> 1, half = tid & 1;
        int g = tile * MT + row;
        bool vld = g < T;
        int src_rn = vld ? g_src[g] : 0;         // (b<<10)|n
        const float4* src = (const float4*)(x +
            ((size_t)src_rn) * DIN + half * 32);
#pragma unroll
        for (int c = 0; c < 4; c++) {
            int kc = half * 4 + c;   // 16B chunk index within row (0..7)
            uint32_t off = (uint32_t)row * 512u + ((uint32_t)(kc ^ (row & 7)) << 4);
            if (vld) {
                float4 a = src[c * 2];
                float4 d = src[c * 2 + 1];
                uint4 w;
                w.x = cvt_h2(a.x, a.y);
                w.y = cvt_h2(a.z, a.w);
                w.z = cvt_h2(d.x, d.y);
                w.w = cvt_h2(d.z, d.w);
                *(uint4*)(smem + SM_A + off) = w;
            } else {
                *(uint4*)(smem + SM_A + off) = make_uint4(0, 0, 0, 0);
            }
        }
    }

    // acc[i*8 + j2]: m16 tile i (rows mw*64+i*16), n8 tile j2 (cols nw*64+j2*8)
    float acc[32][4];
    int gi = 0;

    for (int l = 0; l < 3; l++) {
        const int nch = (l == 0) ? 1 : 4;
#pragma unroll
        for (int i = 0; i < 32; i++) {
            acc[i][0] = 0.f; acc[i][1] = 0.f; acc[i][2] = 0.f; acc[i][3] = 0.f;
        }
        for (int kc = 0; kc < nch; kc++) {
            if (gi + 1 < NCHUNKS) {
                issue_chunk(gi + 1, sb, tid);
                CP_COMMIT();
                CP_WAIT(1);              // chunk gi complete (gi+1 in flight)
            } else {
                CP_WAIT(0);
            }
            __syncthreads();             // publish chunk gi (+ A/epilogue writes)
            uint32_t bbase = sb + SM_B + (uint32_t)(gi % 3) * 32768u;
            uint32_t brow_ = (lane & 7) + ((lane >= 16) ? 8 : 0);
#pragma unroll
            for (int sc = 0; sc < 4; sc++) {
                int ks = kc * 4 + sc;        // k16 index within layer
                uint32_t achk = 2 * ks + (lane >> 4);

                uint32_t af[4][4];
#pragma unroll
                for (int i = 0; i < 4; i++) {
                    uint32_t arow = mw * 64 + i * 16 + (lane & 15);
                    uint32_t aoff = arow * 512u + ((achk ^ (arow & 7)) << 4);
                    ldm4(af[i], sb + SM_A + aoff);
                }

                uint32_t chi = 2 * sc + ((lane >> 3) & 1);
                uint32_t bf[4][4];
#pragma unroll
                for (int j = 0; j < 4; j++) {
                    uint32_t brow = (nw * 4 + j) * 16 + brow_;
                    ldm4(bf[j], bbase + brow * 128u + ((chi ^ (brow & 7)) << 4));
                }

#pragma unroll
                for (int i = 0; i < 4; i++)
#pragma unroll
                    for (int j = 0; j < 4; j++) {
                        mma16816(acc[i * 8 + 2 * j],     af[i], bf[j][0], bf[j][1]);
                        mma16816(acc[i * 8 + 2 * j + 1], af[i], bf[j][2], bf[j][3]);
                    }
            }
            gi++;
        }

        if (l < 2) {
            // epilogue: bias + relu + fp16 -> A smem (warp owns rows mw*64.. x cols nw*64..)
            const float* bias = (const float*)(smem + SM_BIAS) + l * 256;
#pragma unroll
            for (int i = 0; i < 4; i++) {
                int r0 = mw * 64 + i * 16 + gg, r1 = r0 + 8;
#pragma unroll
                for (int j2 = 0; j2 < 8; j2++) {
                    int n0 = nw * 64 + j2 * 8;
                    float b0 = bias[n0 + 2 * t], b1 = bias[n0 + 2 * t + 1];
                    store_one(smem, r0, nw * 8 + j2, t,
                              fmaxf(acc[i * 8 + j2][0] + b0, 0.f),
                              fmaxf(acc[i * 8 + j2][1] + b1, 0.f));
                    store_one(smem, r1, nw * 8 + j2, t,
                              fmaxf(acc[i * 8 + j2][2] + b0, 0.f),
                              fmaxf(acc[i * 8 + j2][3] + b1, 0.f));
                }
            }
            // cross-warp A visibility is ordered by the next chunk's __syncthreads
        } else {
            // ---- segmented pool epilogue ----
            __syncthreads();             // all MMAs done: B buffers reusable
            float* pb = (float*)smem;    // pool buffer: 128 rows x 264 floats
#pragma unroll
            for (int j2 = 0; j2 < 8; j2++) {
                int n0 = nw * 64 + j2 * 8 + 2 * t;
                float b0 = __ldg(pb3 + n0), b1 = __ldg(pb3 + n0 + 1);
#pragma unroll
                for (int i = 0; i < 4; i++) {
                    int r0 = mw * 64 + i * 16 + gg, r1 = r0 + 8;
                    *(float2*)(pb + r0 * 264 + n0) =
                        make_float2(acc[i * 8 + j2][0] + b0, acc[i * 8 + j2][1] + b1);
                    *(float2*)(pb + r1 * 264 + n0) =
                        make_float2(acc[i * 8 + j2][2] + b0, acc[i * 8 + j2][3] + b1);
                }
            }
            int* rowb = (int*)(smem + SM_ROWB);
            if (tid < MT) {
                int g = tile * MT + tid;
                rowb[tid] = (g < T) ? (g_src[g] >> 10) : -1;
            }
            __syncthreads();
            // per-column segmented reduction over 128 rows
            {
                const int c = tid;
                float s = 0.f;
                int curb = rowb[0];
#pragma unroll 16
                for (int r = 0; r < MT; r++) {
                    int bb = rowb[r];
                    if (bb != curb) {
                        if (curb >= 0)
                            g_partial[(g_base[curb] + tile) * HID + c] = s;
                        s = 0.f;
                        curb = bb;
                    }
                    s += pb[r * 264 + c];
                }
                if (curb >= 0)
                    g_partial[(g_base[curb] + tile) * HID + c] = s;
            }
        }
    }
}

// ---------------------------------------------------------------------------
// rho kernel: 64 CTAs x 4 batches — weight reads amortized 4x
// ---------------------------------------------------------------------------
extern "C" __global__ void __launch_bounds__(256, 2)
rho_kernel(const float* __restrict__ rw1, const float* __restrict__ rb1,
           const float* __restrict__ rw2, const float* __restrict__ rb2,
           const float* __restrict__ rw3, const float* __restrict__ rb3,
           float* __restrict__ out)
{
    const int b0  = blockIdx.x * 4;
    const int tid = threadIdx.x;
    __shared__ float p[4][HID];
    __shared__ float o1[4][HID];
    __shared__ float part[2][4][DOUT];

    // gather pooled sums for 4 batches
#pragma unroll
    for (int j = 0; j < 4; j++) {
        float s = 0.f;
        const float* gp = g_partial + (size_t)(b0 + j) * SLOTS * HID + tid;
#pragma unroll
        for (int t = 0; t < SLOTS; t++)
            s += gp[t * HID];
        p[j][tid] = s;
    }
    __syncthreads();

    // layer 1: col = tid, 4 batches share each weight load
    {
        const float* W = rw1 + tid;
        float a0 = 0.f, a1 = 0.f, a2 = 0.f, a3 = 0.f;
#pragma unroll 8
        for (int k = 0; k < HID; k++) {
            float w = W[k * HID];
            a0 = fmaf(p[0][k], w, a0);
            a1 = fmaf(p[1][k], w, a1);
            a2 = fmaf(p[2][k], w, a2);
            a3 = fmaf(p[3][k], w, a3);
        }
        float bb = rb1[tid];
        o1[0][tid] = fmaxf(a0 + bb, 0.f);
        o1[1][tid] = fmaxf(a1 + bb, 0.f);
        o1[2][tid] = fmaxf(a2 + bb, 0.f);
        o1[3][tid] = fmaxf(a3 + bb, 0.f);
    }
    __syncthreads();

    // layer 2 (overwrites p; all p reads finished before previous sync)
    {
        const float* W = rw2 + tid;
        float a0 = 0.f, a1 = 0.f, a2 = 0.f, a3 = 0.f;
#pragma unroll 8
        for (int k = 0; k < HID; k++) {
            float w = W[k * HID];
            a0 = fmaf(o1[0][k], w, a0);
            a1 = fmaf(o1[1][k], w, a1);
            a2 = fmaf(o1[2][k], w, a2);
            a3 = fmaf(o1[3][k], w, a3);
        }
        float bb = rb2[tid];
        p[0][tid] = fmaxf(a0 + bb, 0.f);
        p[1][tid] = fmaxf(a1 + bb, 0.f);
        p[2][tid] = fmaxf(a2 + bb, 0.f);
        p[3][tid] = fmaxf(a3 + bb, 0.f);
    }
    __syncthreads();

    // layer 3: 128 cols, 2-way k split across thread halves
    {
        const int c3 = tid & 127, kh = tid >> 7;
        const float* W = rw3 + (size_t)kh * 128 * DOUT + c3;
        const int kb = kh * 128;
        float a0 = 0.f, a1 = 0.f, a2 = 0.f, a3 = 0.f;
#pragma unroll 8
        for (int k = 0; k < 128; k++) {
            float w = W[k * DOUT];
            a0 = fmaf(p[0][kb + k], w, a0);
            a1 = fmaf(p[1][kb + k], w, a1);
            a2 = fmaf(p[2][kb + k], w, a2);
            a3 = fmaf(p[3][kb + k], w, a3);
        }
        part[kh][0][c3] = a0;
        part[kh][1][c3] = a1;
        part[kh][2][c3] = a2;
        part[kh][3][c3] = a3;
    }
    __syncthreads();
    if (tid < DOUT) {
        float bb = rb3[tid];
#pragma unroll
        for (int j = 0; j < 4; j++) {
            float v = part[0][j][tid] + part[1][j][tid] + bb;
            out[(b0 + j) * DOUT + tid] = (g_cnt[b0 + j] > 0) ? v : 0.f;
        }
    }
}

// ---------------------------------------------------------------------------
extern "C" void kernel_launch(void* const* d_in, const int* in_sizes, int n_in,
                              void* d_out, int out_size)
{
    const float* x    = (const float*)d_in[0];
    const int*   mask = (const int*)  d_in[1];
    const float* pw1  = (const float*)d_in[2];
    const float* pb1  = (const float*)d_in[3];
    const float* pw2  = (const float*)d_in[4];
    const float* pb2  = (const float*)d_in[5];
    const float* pw3  = (const float*)d_in[6];
    const float* pb3  = (const float*)d_in[7];
    const float* rw1  = (const float*)d_in[8];
    const float* rb1  = (const float*)d_in[9];
    const float* rw2  = (const float*)d_in[10];
    const float* rb2  = (const float*)d_in[11];
    const float* rw3  = (const float*)d_in[12];
    const float* rb3  = (const float*)d_in[13];
    float* out = (float*)d_out;

    cudaFuncSetAttribute(phi_kernel,
                         cudaFuncAttributeMaxDynamicSharedMemorySize, SM_BYTES);

    prep_all<<<1088, 256>>>(pw1, pw2, pw3, mask);
    prep3_scatter<<<256, 256>>>();
    phi_kernel<<<MAXTILE, THREADS, SM_BYTES>>>(x, pb1, pb2, pb3);
    rho_kernel<<<64, 256>>>(rw1, rb1, rw2, rb2, rw3, rb3, out);
}

// round 17
// speedup vs baseline: 1.0642x; 1.0642x over previous
#include <cuda_runtime.h>
#include <cuda_fp16.h>
#include <cstdint>

#define B_      256
#define N_      1024
#define DIN     64
#define HID     256
#define DOUT    128
#define MT      128
#define MAXTILE 2048             // worst case: all rows valid
#define SLOTS   10               // max tiles overlapping one batch (<=9) + pad
#define THREADS 256
#define NCHUNKS 9                // k64 chunks: 1 (K=64) + 4 + 4

// smem layout (bytes)
#define SM_B     0                       // 3 buffers x 32768 (B: [256 n][128B = k64 fp16])
#define SM_BIAS  98304                   // 2 * 256 * 4 (pb1, pb2)
#define SM_A     109568                  // A fp16: [128 m][512B row]
#define SM_ROWB  173056                  // 128 ints (row batch ids, epilogue-3)
#define SM_BYTES (109568 + 65536)        // 175104
// epilogue-3 pool buffer reuses bytes [0, 135168): 128 rows x 264 floats

__device__ float g_partial[B_ * SLOTS * HID];
__device__ __align__(16) __half g_wt[147456];
__device__ int g_cnt[B_];
__device__ int g_idx[B_ * N_];
__device__ int g_src[B_ * N_];           // global compacted rows: (b<<10)|n
__device__ int g_base[B_];               // b*SLOTS - (off_b>>7)
__device__ int g_total;
#define WT1 0
#define WT2 16384
#define WT3 81920

// ---------------------------------------------------------------------------
// helpers
// ---------------------------------------------------------------------------
__device__ __forceinline__ uint32_t smem_u32(const void* p) {
    uint32_t a;
    asm("{ .reg .u64 t; cvta.to.shared.u64 t, %1; cvt.u32.u64 %0, t; }"
        : "=r"(a) : "l"(p));
    return a;
}
__device__ __forceinline__ void ldm4(uint32_t r[4], uint32_t addr) {
    asm volatile("ldmatrix.sync.aligned.m8n8.x4.shared.b16 {%0,%1,%2,%3}, [%4];"
                 : "=r"(r[0]), "=r"(r[1]), "=r"(r[2]), "=r"(r[3]) : "r"(addr));
}
__device__ __forceinline__ void mma16816(float c[4], const uint32_t a[4],
                                         uint32_t b0, uint32_t b1) {
    asm volatile(
        "mma.sync.aligned.m16n8k16.row.col.f32.f16.f16.f32 "
        "{%0,%1,%2,%3}, {%4,%5,%6,%7}, {%8,%9}, {%0,%1,%2,%3};"
        : "+f"(c[0]), "+f"(c[1]), "+f"(c[2]), "+f"(c[3])
        : "r"(a[0]), "r"(a[1]), "r"(a[2]), "r"(a[3]), "r"(b0), "r"(b1));
}
__device__ __forceinline__ void cpasync16(uint32_t dst, const void* src) {
    asm volatile("cp.async.ca.shared.global [%0], [%1], 16;" :: "r"(dst), "l"(src));
}
#define CP_COMMIT() asm volatile("cp.async.commit_group;" ::: "memory")
#define CP_WAIT(N)  asm volatile("cp.async.wait_group %0;" :: "n"(N) : "memory")

// pack two fp32 -> f16x2 (v0 -> first element in memory)
__device__ __forceinline__ uint32_t cvt_h2(float v0, float v1) {
    uint32_t r;
    asm("cvt.rn.f16x2.f32 %0, %1, %2;" : "=r"(r) : "f"(v1), "f"(v0));
    return r;
}

// ---------------------------------------------------------------------------
// prep_all: blocks 0..575 weights; 576..831 per-batch compaction;
//           832..1087 zero g_partial
// ---------------------------------------------------------------------------
extern "C" __global__ void __launch_bounds__(256)
prep_all(const float* __restrict__ pw1, const float* __restrict__ pw2,
         const float* __restrict__ pw3, const int* __restrict__ mask)
{
    if (blockIdx.x < 576) {
        int i = blockIdx.x * 256 + threadIdx.x;
        if (i >= 147456) return;
        float v; int dst;
        if (i < 16384) {            // pw1 [64][256] -> [256][64]
            int k = i >> 8, n = i & 255;
            v = pw1[i]; dst = WT1 + n * 64 + k;
        } else if (i < 81920) {     // pw2 [256][256]
            int j = i - 16384; int k = j >> 8, n = j & 255;
            v = pw2[j]; dst = WT2 + n * 256 + k;
        } else {                    // pw3 [256][256]
            int j = i - 81920; int k = j >> 8, n = j & 255;
            v = pw3[j]; dst = WT3 + n * 256 + k;
        }
        g_wt[dst] = __float2half_rn(v);
    } else if (blockIdx.x < 832) {
        const int b = blockIdx.x - 576, tid = threadIdx.x;
        const int lane = tid & 31, wid = tid >> 5;
        const int* mb = mask + b * N_;
        int v[4]; int c = 0;
#pragma unroll
        for (int i = 0; i < 4; i++) { v[i] = (mb[tid * 4 + i] != 0); c += v[i]; }
        int pre = c;
#pragma unroll
        for (int d = 1; d < 32; d <<= 1) {
            int t = __shfl_up_sync(0xffffffffu, pre, d);
            if (lane >= d) pre += t;
        }
        __shared__ int wsum[8];
        if (lane == 31) wsum[wid] = pre;
        __syncthreads();
        int wbase = 0;
#pragma unroll
        for (int w = 0; w < 8; w++)
            if (w < wid) wbase += wsum[w];
        int o = wbase + pre - c;
#pragma unroll
        for (int i = 0; i < 4; i++)
            if (v[i]) g_idx[b * N_ + (o++)] = tid * 4 + i;
        if (tid == 255) g_cnt[b] = wbase + pre;
    } else {
        // zero g_partial slots for batch (blockIdx.x - 832)
        const int b = blockIdx.x - 832;
        float4* dst = (float4*)(g_partial + (size_t)b * SLOTS * HID);
        for (int i = threadIdx.x; i < 640; i += 256)
            dst[i] = make_float4(0.f, 0.f, 0.f, 0.f);
    }
}

// ---------------------------------------------------------------------------
// prep3: every block redundantly scans g_cnt; block b scatters its rows
// ---------------------------------------------------------------------------
extern "C" __global__ void __launch_bounds__(256)
prep3_scatter()
{
    const int b = blockIdx.x, tid = threadIdx.x;
    const int lane = tid & 31, wid = tid >> 5;
    __shared__ int s_excl[256];
    __shared__ int wsum[8];

    int c = g_cnt[tid];
    int pre = c;
#pragma unroll
    for (int d = 1; d < 32; d <<= 1) {
        int t = __shfl_up_sync(0xffffffffu, pre, d);
        if (lane >= d) pre += t;
    }
    if (lane == 31) wsum[wid] = pre;
    __syncthreads();
    int wbase = 0, total = 0;
#pragma unroll
    for (int w = 0; w < 8; w++) {
        if (w < wid) wbase += wsum[w];
        total += wsum[w];
    }
    s_excl[tid] = wbase + pre - c;       // exclusive prefix of batch tid
    __syncthreads();

    const int off = s_excl[b];
    const int cnt = g_cnt[b];
    if (tid == 0) {
        g_base[b] = b * SLOTS - (off >> 7);
        if (b == 0) g_total = total;
    }
    for (int i = tid; i < cnt; i += 256)
        g_src[off + i] = (b << 10) | g_idx[b * N_ + i];
}

// ---------------------------------------------------------------------------
// issue one B chunk (k64) via cp.async into ring buffer gi%3
// ---------------------------------------------------------------------------
__device__ __forceinline__ void issue_chunk(int gi, uint32_t sb, int tid)
{
    const __half* w; int K, kc;
    if (gi == 0)     { w = g_wt + WT1; K = 64;  kc = 0; }
    else if (gi < 5) { w = g_wt + WT2; K = 256; kc = gi - 1; }
    else             { w = g_wt + WT3; K = 256; kc = gi - 5; }
    int n = tid;
    uint32_t dst = sb + SM_B + (uint32_t)(gi % 3) * 32768u + (uint32_t)n * 128u;
    const char* src = (const char*)(w + (size_t)n * K + kc * 64);
#pragma unroll
    for (int c = 0; c < 8; c++)
        cpasync16(dst + ((uint32_t)(c ^ (n & 7)) << 4), src + c * 16);
}

// epilogue store into A smem (fp16), swizzled. chunk = 8-col (16B) group idx
__device__ __forceinline__ void store_one(char* smem, int row, int chunk, int t,
                                          float v0, float v1)
{
    uint32_t h2 = cvt_h2(v0, v1);
    uint32_t off = (uint32_t)row * 512u + ((uint32_t)(chunk ^ (row & 7)) << 4) + t * 4;
    *(uint32_t*)(smem + SM_A + off) = h2;
}

// ---------------------------------------------------------------------------
// phi kernel: globally compacted rows; fp16 MMA, 2(M)x4(N) warp grid;
// segmented pool epilogue
// ---------------------------------------------------------------------------
extern "C" __global__ void __launch_bounds__(THREADS, 1)
phi_kernel(const float* __restrict__ x,
           const float* __restrict__ pb1, const float* __restrict__ pb2,
           const float* __restrict__ pb3)
{
    const int tile = blockIdx.x;
    const int T = g_total;
    if (tile * MT >= T) return;

    extern __shared__ char smem[];
    uint32_t sb = smem_u32(smem);
    const int tid = threadIdx.x, wid = tid >> 5, lane = tid & 31;
    const int mw = wid >> 2, nw = wid & 3;       // 2 x 4 warp grid
    const int gg = lane >> 2, t = lane & 3;

    // issue chunk 0 as early as possible
    issue_chunk(0, sb, tid);
    CP_COMMIT();

    ((float*)(smem + SM_BIAS))[tid]       = pb1[tid];
    ((float*)(smem + SM_BIAS))[256 + tid] = pb2[tid];

    // ---- gather compacted rows -> A smem fp16; zero padding slots
    {
        int row = tid >> 1, half = tid & 1;
        int g = tile * MT + row;
        bool vld = g < T;
        int src_rn = vld ? g_src[g] : 0;         // (b<<10)|n
        const float4* src = (const float4*)(x +
            ((size_t)src_rn) * DIN + half * 32);
#pragma unroll
        for (int c = 0; c < 4; c++) {
            int kc = half * 4 + c;   // 16B chunk index within row (0..7)
            uint32_t off = (uint32_t)row * 512u + ((uint32_t)(kc ^ (row & 7)) << 4);
            if (vld) {
                float4 a = src[c * 2];
                float4 d = src[c * 2 + 1];
                uint4 w;
                w.x = cvt_h2(a.x, a.y);
                w.y = cvt_h2(a.z, a.w);
                w.z = cvt_h2(d.x, d.y);
                w.w = cvt_h2(d.z, d.w);
                *(uint4*)(smem + SM_A + off) = w;
            } else {
                *(uint4*)(smem + SM_A + off) = make_uint4(0, 0, 0, 0);
            }
        }
    }

    // acc[i*8 + j2]: m16 tile i (rows mw*64+i*16), n8 tile j2 (cols nw*64+j2*8)
    float acc[32][4];
    int gi = 0;

    for (int l = 0; l < 3; l++) {
        const int nch = (l == 0) ? 1 : 4;
#pragma unroll
        for (int i = 0; i < 32; i++) {
            acc[i][0] = 0.f; acc[i][1] = 0.f; acc[i][2] = 0.f; acc[i][3] = 0.f;
        }
        for (int kc = 0; kc < nch; kc++) {
            if (gi + 1 < NCHUNKS) {
                issue_chunk(gi + 1, sb, tid);
                CP_COMMIT();
                CP_WAIT(1);              // chunk gi complete (gi+1 in flight)
            } else {
                CP_WAIT(0);
            }
            __syncthreads();             // publish chunk gi (+ A/epilogue writes)
            uint32_t bbase = sb + SM_B + (uint32_t)(gi % 3) * 32768u;
            uint32_t brow_ = (lane & 7) + ((lane >= 16) ? 8 : 0);
#pragma unroll
            for (int sc = 0; sc < 4; sc++) {
                int ks = kc * 4 + sc;        // k16 index within layer
                uint32_t achk = 2 * ks + (lane >> 4);

                uint32_t af[4][4];
#pragma unroll
                for (int i = 0; i < 4; i++) {
                    uint32_t arow = mw * 64 + i * 16 + (lane & 15);
                    uint32_t aoff = arow * 512u + ((achk ^ (arow & 7)) << 4);
                    ldm4(af[i], sb + SM_A + aoff);
                }

                uint32_t chi = 2 * sc + ((lane >> 3) & 1);
                uint32_t bf[4][4];
#pragma unroll
                for (int j = 0; j < 4; j++) {
                    uint32_t brow = (nw * 4 + j) * 16 + brow_;
                    ldm4(bf[j], bbase + brow * 128u + ((chi ^ (brow & 7)) << 4));
                }

#pragma unroll
                for (int i = 0; i < 4; i++)
#pragma unroll
                    for (int j = 0; j < 4; j++) {
                        mma16816(acc[i * 8 + 2 * j],     af[i], bf[j][0], bf[j][1]);
                        mma16816(acc[i * 8 + 2 * j + 1], af[i], bf[j][2], bf[j][3]);
                    }
            }
            gi++;
        }

        if (l < 2) {
            // epilogue: bias + relu + fp16 -> A smem (warp owns rows mw*64.. x cols nw*64..)
            const float* bias = (const float*)(smem + SM_BIAS) + l * 256;
#pragma unroll
            for (int i = 0; i < 4; i++) {
                int r0 = mw * 64 + i * 16 + gg, r1 = r0 + 8;
#pragma unroll
                for (int j2 = 0; j2 < 8; j2++) {
                    int n0 = nw * 64 + j2 * 8;
                    float b0 = bias[n0 + 2 * t], b1 = bias[n0 + 2 * t + 1];
                    store_one(smem, r0, nw * 8 + j2, t,
                              fmaxf(acc[i * 8 + j2][0] + b0, 0.f),
                              fmaxf(acc[i * 8 + j2][1] + b1, 0.f));
                    store_one(smem, r1, nw * 8 + j2, t,
                              fmaxf(acc[i * 8 + j2][2] + b0, 0.f),
                              fmaxf(acc[i * 8 + j2][3] + b1, 0.f));
                }
            }
            // cross-warp A visibility is ordered by the next chunk's __syncthreads
        } else {
            // ---- segmented pool epilogue ----
            __syncthreads();             // all MMAs done: B buffers reusable
            float* pb = (float*)smem;    // pool buffer: 128 rows x 264 floats
#pragma unroll
            for (int j2 = 0; j2 < 8; j2++) {
                int n0 = nw * 64 + j2 * 8 + 2 * t;
                float b0 = __ldg(pb3 + n0), b1 = __ldg(pb3 + n0 + 1);
#pragma unroll
                for (int i = 0; i < 4; i++) {
                    int r0 = mw * 64 + i * 16 + gg, r1 = r0 + 8;
                    *(float2*)(pb + r0 * 264 + n0) =
                        make_float2(acc[i * 8 + j2][0] + b0, acc[i * 8 + j2][1] + b1);
                    *(float2*)(pb + r1 * 264 + n0) =
                        make_float2(acc[i * 8 + j2][2] + b0, acc[i * 8 + j2][3] + b1);
                }
            }
            int* rowb = (int*)(smem + SM_ROWB);
            if (tid < MT) {
                int g = tile * MT + tid;
                rowb[tid] = (g < T) ? (g_src[g] >> 10) : -1;
            }
            __syncthreads();
            // per-column segmented reduction over 128 rows
            {
                const int c = tid;
                float s = 0.f;
                int curb = rowb[0];
#pragma unroll 16
                for (int r = 0; r < MT; r++) {
                    int bb = rowb[r];
                    if (bb != curb) {
                        if (curb >= 0)
                            g_partial[(g_base[curb] + tile) * HID + c] = s;
                        s = 0.f;
                        curb = bb;
                    }
                    s += pb[r * 264 + c];
                }
                if (curb >= 0)
                    g_partial[(g_base[curb] + tile) * HID + c] = s;
            }
        }
    }
}

// ---------------------------------------------------------------------------
// rho kernel: 128 CTAs x 2 batches x 512 threads — weight reads amortized 2x
// while keeping 65K threads of latency hiding
// ---------------------------------------------------------------------------
extern "C" __global__ void __launch_bounds__(512, 2)
rho_kernel(const float* __restrict__ rw1, const float* __restrict__ rb1,
           const float* __restrict__ rw2, const float* __restrict__ rb2,
           const float* __restrict__ rw3, const float* __restrict__ rb3,
           float* __restrict__ out)
{
    const int b0  = blockIdx.x * 2;
    const int tid = threadIdx.x;
    const int col = tid & 255, kh = tid >> 8;     // 2-way k split
    __shared__ float p[2][HID];
    __shared__ float o1[2][HID];
    __shared__ float part[2][2][HID];             // [kh][batch][col]

    // gather pooled sums for 2 batches (512 threads -> one (batch,col) each)
    {
        int j = tid >> 8, c = tid & 255;
        float s = 0.f;
        const float* gp = g_partial + (size_t)(b0 + j) * SLOTS * HID + c;
#pragma unroll
        for (int t = 0; t < SLOTS; t++)
            s += gp[t * HID];
        p[j][c] = s;
    }
    __syncthreads();

    // layer 1: 2-way k split, each weight load feeds both batches
    {
        const float* W = rw1 + (size_t)kh * 128 * HID + col;
        const float* p0 = p[0] + kh * 128;
        const float* p1 = p[1] + kh * 128;
        float a00 = 0.f, a01 = 0.f, a10 = 0.f, a11 = 0.f;
#pragma unroll 8
        for (int k = 0; k < 128; k += 2) {
            float w0 = W[(k)     * HID];
            float w1 = W[(k + 1) * HID];
            a00 = fmaf(p0[k],     w0, a00);
            a10 = fmaf(p1[k],     w0, a10);
            a01 = fmaf(p0[k + 1], w1, a01);
            a11 = fmaf(p1[k + 1], w1, a11);
        }
        part[kh][0][col] = a00 + a01;
        part[kh][1][col] = a10 + a11;
    }
    __syncthreads();
    {
        int j = tid >> 8, c = tid & 255;
        o1[j][c] = fmaxf(part[0][j][c] + part[1][j][c] + rb1[c], 0.f);
    }
    __syncthreads();

    // layer 2
    {
        const float* W = rw2 + (size_t)kh * 128 * HID + col;
        const float* p0 = o1[0] + kh * 128;
        const float* p1 = o1[1] + kh * 128;
        float a00 = 0.f, a01 = 0.f, a10 = 0.f, a11 = 0.f;
#pragma unroll 8
        for (int k = 0; k < 128; k += 2) {
            float w0 = W[(k)     * HID];
            float w1 = W[(k + 1) * HID];
            a00 = fmaf(p0[k],     w0, a00);
            a10 = fmaf(p1[k],     w0, a10);
            a01 = fmaf(p0[k + 1], w1, a01);
            a11 = fmaf(p1[k + 1], w1, a11);
        }
        part[kh][0][col] = a00 + a01;
        part[kh][1][col] = a10 + a11;
    }
    __syncthreads();
    {
        int j = tid >> 8, c = tid & 255;
        p[j][c] = fmaxf(part[0][j][c] + part[1][j][c] + rb2[c], 0.f);
    }
    __syncthreads();

    // layer 3: 128 cols, 4-way k split (64 k each), both batches
    {
        const int c3 = tid & 127, k4 = tid >> 7;
        const float* W = rw3 + (size_t)k4 * 64 * DOUT + c3;
        const float* p0 = p[0] + k4 * 64;
        const float* p1 = p[1] + k4 * 64;
        float a00 = 0.f, a01 = 0.f, a10 = 0.f, a11 = 0.f;
#pragma unroll 8
        for (int k = 0; k < 64; k += 2) {
            float w0 = W[(k)     * DOUT];
            float w1 = W[(k + 1) * DOUT];
            a00 = fmaf(p0[k],     w0, a00);
            a10 = fmaf(p1[k],     w0, a10);
            a01 = fmaf(p0[k + 1], w1, a01);
            a11 = fmaf(p1[k + 1], w1, a11);
        }
        // part viewed as [4 k-groups][2 batches][128 cols]
        float* pt = &part[0][0][0];
        pt[(k4 * 2 + 0) * DOUT + c3] = a00 + a01;
        pt[(k4 * 2 + 1) * DOUT + c3] = a10 + a11;
    }
    __syncthreads();
    if (tid < 2 * DOUT) {
        int j = tid >> 7, c = tid & 127;
        const float* pt = &part[0][0][0];
        float v = pt[(0 * 2 + j) * DOUT + c] + pt[(1 * 2 + j) * DOUT + c]
                + pt[(2 * 2 + j) * DOUT + c] + pt[(3 * 2 + j) * DOUT + c]
                + rb3[c];
        out[(b0 + j) * DOUT + c] = (g_cnt[b0 + j] > 0) ? v : 0.f;
    }
}

// ---------------------------------------------------------------------------
extern "C" void kernel_launch(void* const* d_in, const int* in_sizes, int n_in,
                              void* d_out, int out_size)
{
    const float* x    = (const float*)d_in[0];
    const int*   mask = (const int*)  d_in[1];
    const float* pw1  = (const float*)d_in[2];
    const float* pb1  = (const float*)d_in[3];
    const float* pw2  = (const float*)d_in[4];
    const float* pb2  = (const float*)d_in[5];
    const float* pw3  = (const float*)d_in[6];
    const float* pb3  = (const float*)d_in[7];
    const float* rw1  = (const float*)d_in[8];
    const float* rb1  = (const float*)d_in[9];
    const float* rw2  = (const float*)d_in[10];
    const float* rb2  = (const float*)d_in[11];
    const float* rw3  = (const float*)d_in[12];
    const float* rb3  = (const float*)d_in[13];
    float* out = (float*)d_out;

    cudaFuncSetAttribute(phi_kernel,
                         cudaFuncAttributeMaxDynamicSharedMemorySize, SM_BYTES);

    prep_all<<<1088, 256>>>(pw1, pw2, pw3, mask);
    prep3_scatter<<<256, 256>>>();
    phi_kernel<<<MAXTILE, THREADS, SM_BYTES>>>(x, pb1, pb2, pb3);
    rho_kernel<<<128, 512>>>(rw1, rb1, rw2, rb2, rw3, rb3, out);
}